// round 1
// baseline (speedup 1.0000x reference)
#include <cuda_runtime.h>
#include <cstdint>

// Problem constants (fixed shapes for this problem)
#define BATCH    128
#define SEQT     256
#define HID      128
#define WIN      16
#define NWIN     (SEQT - WIN)       // 240 windows
#define NSTEP    (NWIN * WIN)       // 3840 chained LSTM steps
#define NROWS    (4 * HID)          // 512 gate rows
#define NTHREADS 512

// Weight storage split per gate-row (128 k-values):
//   k in [0, 96)  -> registers (48 packed f32x2 pairs per thread)
//   k in [96,128) -> shared memory (8 x ulonglong2 per row = 32 floats)
#define KRP 48   // register pairs
#define KSB 8    // smem ulonglong2 blocks

typedef unsigned long long u64;

__device__ __forceinline__ void fma2(u64& d, u64 a, u64 b) {
    // packed f32x2 FMA: d = a*b + d  (2 fp32 FMAs per instruction, Blackwell)
    asm("fma.rn.f32x2 %0, %1, %2, %0;" : "+l"(d) : "l"(a), "l"(b));
}
__device__ __forceinline__ u64 pk2(float lo, float hi) {
    u64 r; asm("mov.b64 %0, {%1, %2};" : "=l"(r) : "f"(lo), "f"(hi)); return r;
}
__device__ __forceinline__ float2 upk2(u64 v) {
    float2 r; asm("mov.b64 {%0, %1}, %2;" : "=f"(r.x), "=f"(r.y) : "l"(v)); return r;
}
// Flag-proof fast-accurate nonlinearities (MUFU ex2 based, ~1e-7 rel err)
__device__ __forceinline__ float sigm(float x)     { return 1.f / (1.f + __expf(-x)); }
__device__ __forceinline__ float tanh_acc(float x) { return 1.f - 2.f / (__expf(2.f * x) + 1.f); }

// Dynamic smem layout (bytes)
#define OFF_WS   0                              // ulonglong2[KSB*NROWS] = 8*512*16 = 65536
#define OFF_X    65536                          // float[256]
#define OFF_H    (65536 + 1024)                 // float[128]
#define OFF_G    (65536 + 1024 + 512)           // float[512]
#define OFF_RED  (65536 + 1024 + 512 + 2048)    // float[4]
#define SMEM_BYTES (OFF_RED + 64)               // 69184 B

__global__ void __launch_bounds__(NTHREADS, 1)
lstm_persistent_kernel(const float* __restrict__ x,
                       const float* __restrict__ W_ih,
                       const float* __restrict__ W_hh,
                       const float* __restrict__ b_ih,
                       const float* __restrict__ b_hh,
                       const float* __restrict__ fc_W,
                       const float* __restrict__ fc_b,
                       float* __restrict__ out)
{
    extern __shared__ char smem[];
    ulonglong2* sws  = (ulonglong2*)(smem + OFF_WS);
    float*      sx   = (float*)(smem + OFF_X);
    float*      shv  = (float*)(smem + OFF_H);
    float*      sg   = (float*)(smem + OFF_G);
    float*      sred = (float*)(smem + OFF_RED);

    const int j = threadIdx.x;       // gate row 0..511
    const int b = blockIdx.x;        // batch chain 0..127

    // ---------------- Prologue: load weights/state (once per launch) --------
    const float* wrow = W_hh + j * HID;   // row j of (512,128) row-major

    u64 wreg[KRP];
#pragma unroll
    for (int m = 0; m < KRP; ++m)
        wreg[m] = ((const u64*)wrow)[m];             // k = 2m, 2m+1

#pragma unroll
    for (int kb = 0; kb < KSB; ++kb)                  // k = 96+4kb .. 96+4kb+3
        sws[kb * NROWS + j] = ((const ulonglong2*)(wrow + 2 * KRP))[kb];

    const float bias = b_ih[j] + b_hh[j];
    const float wih  = W_ih[j];                       // W_ih is (512,1)
    const float fcw  = (j < HID) ? fc_W[j] : 0.f;     // fc_W is (1,128)
    const float fcb  = fc_b[0];
    float c = 0.f;                                    // cell state lives in reg (j<HID)

    if (j < HID)  shv[j] = 0.f;                       // h0 = 0
    if (j < SEQT) sx[j] = x[b * SEQT + j];            // this chain's x row
    if (j < WIN)  out[b * SEQT + j] = x[b * SEQT + j];// out[:, :16] = x[:, :16]
    __syncthreads();

    // ---------------- 3840 chained LSTM steps ------------------------------
    for (int s = 0; s < NSTEP; ++s) {
        const float xt = sx[(s >> 4) + (s & (WIN - 1))];   // x[b, w + s%16]

        u64 acc = pk2(__fmaf_rn(xt, wih, bias), 0.f);
        const ulonglong2* h2v = (const ulonglong2*)shv;    // broadcast LDS.128

#pragma unroll
        for (int m = 0; m < 24; ++m) {                     // k = 0..95 (reg weights)
            ulonglong2 hv = h2v[m];                        // h[4m..4m+3]
            fma2(acc, wreg[2 * m],     hv.x);
            fma2(acc, wreg[2 * m + 1], hv.y);
        }
#pragma unroll
        for (int kb = 0; kb < KSB; ++kb) {                 // k = 96..127 (smem weights)
            ulonglong2 wv = sws[kb * NROWS + j];
            ulonglong2 hv = h2v[24 + kb];
            fma2(acc, wv.x, hv.x);
            fma2(acc, wv.y, hv.y);
        }
        float2 a2 = upk2(acc);
        sg[j] = a2.x + a2.y;                               // raw gate row j
        __syncthreads();

        // Gate combine: hidden unit j handled by thread j (warps 0..3)
        if (j < HID) {
            const float gi = sg[j];
            const float gf = sg[j + HID];
            const float gg = sg[j + 2 * HID];
            const float go = sg[j + 3 * HID];
            c = sigm(gf) * c + sigm(gi) * tanh_acc(gg);
            const float h = sigm(go) * tanh_acc(c);
            shv[j] = h;

            if ((s & (WIN - 1)) == (WIN - 1)) {            // window tap
                float p = fcw * h;
                p += __shfl_down_sync(0xffffffffu, p, 16);
                p += __shfl_down_sync(0xffffffffu, p, 8);
                p += __shfl_down_sync(0xffffffffu, p, 4);
                p += __shfl_down_sync(0xffffffffu, p, 2);
                p += __shfl_down_sync(0xffffffffu, p, 1);
                if ((j & 31) == 0) sred[j >> 5] = p;
            }
        }
        __syncthreads();

        if (((s & (WIN - 1)) == (WIN - 1)) && j == 0) {
            float v = sred[0] + sred[1] + sred[2] + sred[3] + fcb;
            out[b * SEQT + WIN + (s >> 4)] = (v >= 0.f) ? v : 0.3f * v;
        }
    }
}

extern "C" void kernel_launch(void* const* d_in, const int* in_sizes, int n_in,
                              void* d_out, int out_size)
{
    const float* x    = (const float*)d_in[0];
    const float* W_ih = (const float*)d_in[1];
    const float* W_hh = (const float*)d_in[2];
    const float* b_ih = (const float*)d_in[3];
    const float* b_hh = (const float*)d_in[4];
    const float* fc_W = (const float*)d_in[5];
    const float* fc_b = (const float*)d_in[6];
    // d_in[7] = pred_fut (unused)

    cudaFuncSetAttribute(lstm_persistent_kernel,
                         cudaFuncAttributeMaxDynamicSharedMemorySize, SMEM_BYTES);
    lstm_persistent_kernel<<<BATCH, NTHREADS, SMEM_BYTES>>>(
        x, W_ih, W_hh, b_ih, b_hh, fc_W, fc_b, (float*)d_out);
}

// round 2
// speedup vs baseline: 1.1114x; 1.1114x over previous
#include <cuda_runtime.h>
#include <cuda_fp16.h>

// Problem constants
#define BATCH    128
#define SEQT     256
#define HID      128
#define WIN      16
#define NSTEP    3840          // (256-16)*16 chained LSTM steps
#define NROWS    512           // 4*HID gate rows
#define NTHREADS 512           // 16 warps; warp w owns gate rows [32w, 32w+32)

// Fast nonlinearities (MUFU-based, ~1e-7 rel err)
__device__ __forceinline__ float sigm(float x)     { return 1.f / (1.f + __expf(-x)); }
__device__ __forceinline__ float tanh_acc(float x) { return 1.f - 2.f / (__expf(2.f * x) + 1.f); }

__device__ __forceinline__ unsigned pack_h2(float lo, float hi) {
    __half2 h = __floats2half2_rn(lo, hi);
    return *reinterpret_cast<unsigned*>(&h);
}

// m16n8k16 row.col f16*f16 -> f32 accumulate (warp-level HMMA)
__device__ __forceinline__ void mma16816(float* c, const unsigned* a, unsigned b0, unsigned b1) {
    asm volatile(
        "mma.sync.aligned.m16n8k16.row.col.f32.f16.f16.f32 "
        "{%0,%1,%2,%3},{%4,%5,%6,%7},{%8,%9},{%0,%1,%2,%3};\n"
        : "+f"(c[0]), "+f"(c[1]), "+f"(c[2]), "+f"(c[3])
        : "r"(a[0]), "r"(a[1]), "r"(a[2]), "r"(a[3]), "r"(b0), "r"(b1));
}

__global__ void __launch_bounds__(NTHREADS, 1)
lstm_mma_kernel(const float* __restrict__ x,
                const float* __restrict__ W_ih,
                const float* __restrict__ W_hh,
                const float* __restrict__ b_ih,
                const float* __restrict__ b_hh,
                const float* __restrict__ fc_W,
                const float* __restrict__ fc_b,
                float* __restrict__ out)
{
    __shared__ float sx[SEQT];
    __shared__ float sg[NROWS];
    __shared__ __align__(16) __half sh_hi[HID];   // h, fp16 high part
    __shared__ __align__(16) __half sh_lo[HID];   // h residual, fp16
    __shared__ float sred[4];

    const int tid = threadIdx.x;
    const int b   = blockIdx.x;
    const int w   = tid >> 5;          // warp 0..15
    const int l   = tid & 31;
    const int gid = l >> 2;            // 0..7
    const int tg  = l & 3;             // 0..3

    // ---------------- Prologue: build A fragments (W_hh as fp16, in RF) ----
    // Warp w, tile t (t=0,1): gate rows R..R+15 with R = 32w + 16t.
    // m16n8k16 A-frag: a0:(row gid,  k 2tg..+1)  a1:(row gid+8, k 2tg..+1)
    //                  a2:(row gid,  k 2tg+8..)  a3:(row gid+8, k 2tg+8..)
    unsigned Afrag[2][8][4];
#pragma unroll
    for (int t = 0; t < 2; ++t) {
        const int R = 32 * w + 16 * t;
        const float* r0 = W_hh + (R + gid)     * HID;
        const float* r8 = W_hh + (R + gid + 8) * HID;
#pragma unroll
        for (int kk = 0; kk < 8; ++kk) {
            const int k0 = 16 * kk + 2 * tg;
            Afrag[t][kk][0] = pack_h2(r0[k0],     r0[k0 + 1]);
            Afrag[t][kk][1] = pack_h2(r8[k0],     r8[k0 + 1]);
            Afrag[t][kk][2] = pack_h2(r0[k0 + 8], r0[k0 + 9]);
            Afrag[t][kk][3] = pack_h2(r8[k0 + 8], r8[k0 + 9]);
        }
    }

    // Per-lane bias / W_ih for this lane's rows (rows gid, gid+8 of each tile)
    float biasr[2][2], wihr[2][2];
#pragma unroll
    for (int t = 0; t < 2; ++t) {
        const int R = 32 * w + 16 * t;
        biasr[t][0] = b_ih[R + gid]     + b_hh[R + gid];
        biasr[t][1] = b_ih[R + gid + 8] + b_hh[R + gid + 8];
        wihr[t][0]  = W_ih[R + gid];
        wihr[t][1]  = W_ih[R + gid + 8];
    }

    const float fcw = (tid < HID) ? fc_W[tid] : 0.f;
    const float fcb = fc_b[0];
    float c_state = 0.f;

    if (tid < HID) { sh_hi[tid] = __float2half_rn(0.f); sh_lo[tid] = __float2half_rn(0.f); }
    if (tid < SEQT) sx[tid] = x[b * SEQT + tid];
    if (tid < WIN)  out[b * SEQT + tid] = x[b * SEQT + tid];
    __syncthreads();

    // ---------------- 3840 chained steps -----------------------------------
    for (int s = 0; s < NSTEP; ++s) {
        const float xt = sx[(s >> 4) + (s & (WIN - 1))];

        // Accumulators: chain A (k-steps 0..3), chain B (k-steps 4..7).
        // B is h replicated across all 8 N-columns, so every D column equals
        // the gate value -> init ALL cols with bias so they stay identical.
        float cA[2][4], cB[2][4];
#pragma unroll
        for (int t = 0; t < 2; ++t) {
            cA[t][0] = __fmaf_rn(xt, wihr[t][0], biasr[t][0]);
            cA[t][1] = cA[t][0];
            cA[t][2] = __fmaf_rn(xt, wihr[t][1], biasr[t][1]);
            cA[t][3] = cA[t][2];
            cB[t][0] = 0.f; cB[t][1] = 0.f; cB[t][2] = 0.f; cB[t][3] = 0.f;
        }

        // hi part of h
#pragma unroll
        for (int kk = 0; kk < 4; ++kk) {
            unsigned b0 = *(const unsigned*)(sh_hi + 16 * kk + 2 * tg);
            unsigned b1 = *(const unsigned*)(sh_hi + 16 * kk + 8 + 2 * tg);
            mma16816(cA[0], Afrag[0][kk], b0, b1);
            mma16816(cA[1], Afrag[1][kk], b0, b1);
        }
#pragma unroll
        for (int kk = 4; kk < 8; ++kk) {
            unsigned b0 = *(const unsigned*)(sh_hi + 16 * kk + 2 * tg);
            unsigned b1 = *(const unsigned*)(sh_hi + 16 * kk + 8 + 2 * tg);
            mma16816(cB[0], Afrag[0][kk], b0, b1);
            mma16816(cB[1], Afrag[1][kk], b0, b1);
        }
        // lo (residual) part of h -> full fp32-accuracy h contribution
#pragma unroll
        for (int kk = 0; kk < 4; ++kk) {
            unsigned b0 = *(const unsigned*)(sh_lo + 16 * kk + 2 * tg);
            unsigned b1 = *(const unsigned*)(sh_lo + 16 * kk + 8 + 2 * tg);
            mma16816(cA[0], Afrag[0][kk], b0, b1);
            mma16816(cA[1], Afrag[1][kk], b0, b1);
        }
#pragma unroll
        for (int kk = 4; kk < 8; ++kk) {
            unsigned b0 = *(const unsigned*)(sh_lo + 16 * kk + 2 * tg);
            unsigned b1 = *(const unsigned*)(sh_lo + 16 * kk + 8 + 2 * tg);
            mma16816(cB[0], Afrag[0][kk], b0, b1);
            mma16816(cB[1], Afrag[1][kk], b0, b1);
        }

        // All D columns identical; lane tg==0 stores its two rows per tile.
        if (tg == 0) {
#pragma unroll
            for (int t = 0; t < 2; ++t) {
                const int R = 32 * w + 16 * t;
                sg[R + gid]     = cA[t][0] + cB[t][0];
                sg[R + gid + 8] = cA[t][2] + cB[t][2];
            }
        }
        __syncthreads();

        // Gate combine: hidden unit tid (warps 0..3)
        if (tid < HID) {
            const float gi = sg[tid];
            const float gf = sg[tid + HID];
            const float gg = sg[tid + 2 * HID];
            const float go = sg[tid + 3 * HID];
            c_state = sigm(gf) * c_state + sigm(gi) * tanh_acc(gg);
            const float h = sigm(go) * tanh_acc(c_state);

            const __half hh = __float2half_rn(h);
            sh_hi[tid] = hh;
            sh_lo[tid] = __float2half_rn(h - __half2float(hh));

            if ((s & (WIN - 1)) == (WIN - 1)) {            // fc tap at t=15
                float p = fcw * h;
                p += __shfl_down_sync(0xffffffffu, p, 16);
                p += __shfl_down_sync(0xffffffffu, p, 8);
                p += __shfl_down_sync(0xffffffffu, p, 4);
                p += __shfl_down_sync(0xffffffffu, p, 2);
                p += __shfl_down_sync(0xffffffffu, p, 1);
                if ((l & 31) == 0) sred[tid >> 5] = p;
            }
        }
        __syncthreads();

        if (((s & (WIN - 1)) == (WIN - 1)) && tid == 0) {
            float v = sred[0] + sred[1] + sred[2] + sred[3] + fcb;
            out[b * SEQT + WIN + (s >> 4)] = (v >= 0.f) ? v : 0.3f * v;
        }
    }
}

extern "C" void kernel_launch(void* const* d_in, const int* in_sizes, int n_in,
                              void* d_out, int out_size)
{
    const float* x    = (const float*)d_in[0];
    const float* W_ih = (const float*)d_in[1];
    const float* W_hh = (const float*)d_in[2];
    const float* b_ih = (const float*)d_in[3];
    const float* b_hh = (const float*)d_in[4];
    const float* fc_W = (const float*)d_in[5];
    const float* fc_b = (const float*)d_in[6];

    lstm_mma_kernel<<<BATCH, NTHREADS>>>(
        x, W_ih, W_hh, b_ih, b_hh, fc_W, fc_b, (float*)d_out);
}

// round 4
// speedup vs baseline: 1.7019x; 1.5313x over previous
#include <cuda_runtime.h>
#include <cuda_fp16.h>

// Problem constants
#define BATCH    128
#define SEQT     256
#define HID      128
#define WIN      16
#define NSTEP    3840          // (256-16)*16 chained LSTM steps
#define NROWS    512           // 4*HID gate rows
#define NTHREADS 512           // 16 warps; warp w owns gate rows [32w, 32w+32)

// HW tanh (MUFU.TANH, ~5e-4 max err) and sigmoid via tanh
__device__ __forceinline__ float tanh_fast(float x) {
    float y; asm("tanh.approx.f32 %0, %1;" : "=f"(y) : "f"(x)); return y;
}
__device__ __forceinline__ float sigm_fast(float x) {
    return __fmaf_rn(0.5f, tanh_fast(0.5f * x), 0.5f);
}

__device__ __forceinline__ unsigned pack_h2(float lo, float hi) {
    __half2 h = __floats2half2_rn(lo, hi);
    return *reinterpret_cast<unsigned*>(&h);
}

// m16n8k16 row.col f16*f16 -> f32 accumulate (warp-level HMMA)
__device__ __forceinline__ void mma16816(float* c, const unsigned* a, unsigned b0, unsigned b1) {
    asm volatile(
        "mma.sync.aligned.m16n8k16.row.col.f32.f16.f16.f32 "
        "{%0,%1,%2,%3},{%4,%5,%6,%7},{%8,%9},{%0,%1,%2,%3};\n"
        : "+f"(c[0]), "+f"(c[1]), "+f"(c[2]), "+f"(c[3])
        : "r"(a[0]), "r"(a[1]), "r"(a[2]), "r"(a[3]), "r"(b0), "r"(b1));
}

__global__ void __launch_bounds__(NTHREADS, 1)
lstm_mma2_kernel(const float* __restrict__ x,
                 const float* __restrict__ W_ih,
                 const float* __restrict__ W_hh,
                 const float* __restrict__ b_ih,
                 const float* __restrict__ b_hh,
                 const float* __restrict__ fc_W,
                 const float* __restrict__ fc_b,
                 float* __restrict__ out)
{
    __shared__ float sx[SEQT];
    __shared__ float sg_hi[NROWS];                    // W.h_hi per gate row
    __shared__ float sg_lo[NROWS];                    // W.h_lo per gate row
    __shared__ __align__(16) __half sh_hi[HID];       // h (fp16 high)
    __shared__ __align__(16) __half sh_lo[HID];       // h residual (fp16)
    __shared__ __align__(16) __half sh_zero[HID];     // constant zeros (B cols 1-3,5-7)
    __shared__ float sred[4];

    const int tid = threadIdx.x;
    const int b   = blockIdx.x;
    const int w   = tid >> 5;          // warp 0..15
    const int l   = tid & 31;
    const int gid = l >> 2;            // 0..7  (= D-frag row group, B-frag column)
    const int tg  = l & 3;             // 0..3

    // ---------------- Prologue: A fragments (W_hh fp16, resident in RF) ----
    // Warp w, tile t: gate rows R..R+15, R = 32w + 16t.
    unsigned Afrag[2][8][4];
#pragma unroll
    for (int t = 0; t < 2; ++t) {
        const int R = 32 * w + 16 * t;
        const float* r0 = W_hh + (R + gid)     * HID;
        const float* r8 = W_hh + (R + gid + 8) * HID;
#pragma unroll
        for (int kk = 0; kk < 8; ++kk) {
            const int k0 = 16 * kk + 2 * tg;
            Afrag[t][kk][0] = pack_h2(r0[k0],     r0[k0 + 1]);
            Afrag[t][kk][1] = pack_h2(r8[k0],     r8[k0 + 1]);
            Afrag[t][kk][2] = pack_h2(r0[k0 + 8], r0[k0 + 9]);
            Afrag[t][kk][3] = pack_h2(r8[k0 + 8], r8[k0 + 9]);
        }
    }

    // Per-lane bias / W_ih for rows (gid, gid+8) of each tile (used by tg==0)
    float biasr[2][2], wihr[2][2];
#pragma unroll
    for (int t = 0; t < 2; ++t) {
        const int R = 32 * w + 16 * t;
        biasr[t][0] = b_ih[R + gid]     + b_hh[R + gid];
        biasr[t][1] = b_ih[R + gid + 8] + b_hh[R + gid + 8];
        wihr[t][0]  = W_ih[R + gid];
        wihr[t][1]  = W_ih[R + gid + 8];
    }

    const float fcw = (tid < HID) ? fc_W[tid] : 0.f;
    const float fcb = fc_b[0];
    float c_state = 0.f;

    if (tid < HID) {
        sh_hi[tid]   = __float2half_rn(0.f);
        sh_lo[tid]   = __float2half_rn(0.f);
        sh_zero[tid] = __float2half_rn(0.f);
    }
    if (tid < SEQT) sx[tid] = x[b * SEQT + tid];
    if (tid < WIN)  out[b * SEQT + tid] = x[b * SEQT + tid];
    __syncthreads();

    // B-operand pointer for this lane's column (n = gid):
    //   n==0 -> h_hi, n==4 -> h_lo, else zeros (never written)
    const __half* bp = (gid == 0) ? sh_hi : (gid == 4) ? sh_lo : sh_zero;

    // ---------------- 3840 chained steps -----------------------------------
    for (int s = 0; s < NSTEP; ++s) {
        const float xt = sx[(s >> 4) + (s & (WIN - 1))];

        // Two half-depth accumulation chains per tile: cA (kk 0..3), cB (kk 4..7)
        float cA[2][4], cB[2][4];
#pragma unroll
        for (int t = 0; t < 2; ++t) {
            if (tg == 0) {   // D column 0 gets bias + x*W_ih folded in
                cA[t][0] = __fmaf_rn(xt, wihr[t][0], biasr[t][0]);
                cA[t][2] = __fmaf_rn(xt, wihr[t][1], biasr[t][1]);
            } else {
                cA[t][0] = 0.f; cA[t][2] = 0.f;
            }
            cA[t][1] = 0.f; cA[t][3] = 0.f;
            cB[t][0] = 0.f; cB[t][1] = 0.f; cB[t][2] = 0.f; cB[t][3] = 0.f;
        }

#pragma unroll
        for (int kk = 0; kk < 4; ++kk) {
            unsigned b0 = *(const unsigned*)(bp + 16 * kk + 2 * tg);
            unsigned b1 = *(const unsigned*)(bp + 16 * kk + 8 + 2 * tg);
            mma16816(cA[0], Afrag[0][kk], b0, b1);
            mma16816(cA[1], Afrag[1][kk], b0, b1);
        }
#pragma unroll
        for (int kk = 4; kk < 8; ++kk) {
            unsigned b0 = *(const unsigned*)(bp + 16 * kk + 2 * tg);
            unsigned b1 = *(const unsigned*)(bp + 16 * kk + 8 + 2 * tg);
            mma16816(cB[0], Afrag[0][kk], b0, b1);
            mma16816(cB[1], Afrag[1][kk], b0, b1);
        }

        // col0 (W.h_hi) lives in lanes tg==0; col4 (W.h_lo) in lanes tg==2.
        if (tg == 0) {
#pragma unroll
            for (int t = 0; t < 2; ++t) {
                const int R = 32 * w + 16 * t;
                sg_hi[R + gid]     = cA[t][0] + cB[t][0];
                sg_hi[R + gid + 8] = cA[t][2] + cB[t][2];
            }
        } else if (tg == 2) {
#pragma unroll
            for (int t = 0; t < 2; ++t) {
                const int R = 32 * w + 16 * t;
                sg_lo[R + gid]     = cA[t][0] + cB[t][0];
                sg_lo[R + gid + 8] = cA[t][2] + cB[t][2];
            }
        }
        __syncthreads();

        // Gate combine: hidden unit tid (warps 0..3)
        if (tid < HID) {
            const float gi = sg_hi[tid]           + sg_lo[tid];
            const float gf = sg_hi[tid + HID]     + sg_lo[tid + HID];
            const float gg = sg_hi[tid + 2 * HID] + sg_lo[tid + 2 * HID];
            const float go = sg_hi[tid + 3 * HID] + sg_lo[tid + 3 * HID];
            c_state = sigm_fast(gf) * c_state + sigm_fast(gi) * tanh_fast(gg);
            const float h = sigm_fast(go) * tanh_fast(c_state);

            const __half hh = __float2half_rn(h);
            sh_hi[tid] = hh;
            sh_lo[tid] = __float2half_rn(h - __half2float(hh));

            if ((s & (WIN - 1)) == (WIN - 1)) {            // fc tap at t=15
                float p = fcw * h;
                p += __shfl_down_sync(0xffffffffu, p, 16);
                p += __shfl_down_sync(0xffffffffu, p, 8);
                p += __shfl_down_sync(0xffffffffu, p, 4);
                p += __shfl_down_sync(0xffffffffu, p, 2);
                p += __shfl_down_sync(0xffffffffu, p, 1);
                if ((l & 31) == 0) sred[tid >> 5] = p;
            }
        }
        __syncthreads();

        if (((s & (WIN - 1)) == (WIN - 1)) && tid == 0) {
            float v = sred[0] + sred[1] + sred[2] + sred[3] + fcb;
            out[b * SEQT + WIN + (s >> 4)] = (v >= 0.f) ? v : 0.3f * v;
        }
    }
}

extern "C" void kernel_launch(void* const* d_in, const int* in_sizes, int n_in,
                              void* d_out, int out_size)
{
    const float* x    = (const float*)d_in[0];
    const float* W_ih = (const float*)d_in[1];
    const float* W_hh = (const float*)d_in[2];
    const float* b_ih = (const float*)d_in[3];
    const float* b_hh = (const float*)d_in[4];
    const float* fc_W = (const float*)d_in[5];
    const float* fc_b = (const float*)d_in[6];

    lstm_mma2_kernel<<<BATCH, NTHREADS>>>(
        x, W_ih, W_hh, b_ih, b_hh, fc_W, fc_b, (float*)d_out);
}